// round 1
// baseline (speedup 1.0000x reference)
#include <cuda_runtime.h>

// ---------------------------------------------------------------------------
// SkinDeformNet: linear blend skinning.
// Kernel A (rig): Rodrigues + kinematic chain -> Rs, Js_transformed, A16 scratch.
// Kernel B (pts): per-point T = ws @ A16[batch], out3 = T * [p,1].
// ---------------------------------------------------------------------------

#define NB_MAX 16           // max distinct batches cached in smem per block
#define MAX_B  64

__device__ __align__(16) float g_A[MAX_B * 24 * 16];   // A16 scratch

__device__ const int c_par[24]   = {-1,0,0,0,1,2,3,4,5,6,7,8,9,9,9,12,13,14,16,17,18,19,20,21};
__device__ const int c_depth[24] = { 0,1,1,1,2,2,2,3,3,3,4,4,4,4,4, 5, 5, 5, 6, 6, 7, 7, 8, 8};

// ============================= Kernel A: rig ===============================
__global__ void rig_kernel(const float* __restrict__ Js,
                           const float* __restrict__ poses,
                           float* __restrict__ outRs,
                           float* __restrict__ outJt)
{
    const int b = blockIdx.x;
    const int j = threadIdx.x;      // 32 threads, j<24 active

    __shared__ float sJ[24][3];
    __shared__ float sRes[24][12];  // 3x4 rows of the chained transform

    float R[9];
    if (j < 24) {
        float rx = poses[b*72 + j*3 + 0];
        float ry = poses[b*72 + j*3 + 1];
        float rz = poses[b*72 + j*3 + 2];
        float ang = sqrtf(rx*rx + ry*ry + rz*rz) + 1e-8f;
        float inv = 1.0f / ang;
        float x = rx*inv, y = ry*inv, z = rz*inv;
        float s = sinf(ang), c = cosf(ang);
        float o = 1.0f - c;
        R[0] = 1.0f - o*(y*y + z*z);
        R[1] = -s*z + o*(x*y);
        R[2] =  s*y + o*(x*z);
        R[3] =  s*z + o*(x*y);
        R[4] = 1.0f - o*(x*x + z*z);
        R[5] = -s*x + o*(y*z);
        R[6] = -s*y + o*(x*z);
        R[7] =  s*x + o*(y*z);
        R[8] = 1.0f - o*(x*x + y*y);
        #pragma unroll
        for (int i = 0; i < 9; i++) outRs[b*216 + j*9 + i] = R[i];
        sJ[j][0] = Js[b*72 + j*3 + 0];
        sJ[j][1] = Js[b*72 + j*3 + 1];
        sJ[j][2] = Js[b*72 + j*3 + 2];
    }
    __syncthreads();

    float res[12];
    const int dj = (j < 24) ? c_depth[j] : -1;
    for (int lv = 0; lv < 9; lv++) {
        if (dj == lv) {
            if (j == 0) {
                res[0]=R[0]; res[1]=R[1]; res[2] =R[2]; res[3] =sJ[0][0];
                res[4]=R[3]; res[5]=R[4]; res[6] =R[5]; res[7] =sJ[0][1];
                res[8]=R[6]; res[9]=R[7]; res[10]=R[8]; res[11]=sJ[0][2];
            } else {
                int p = c_par[j];
                float tx = sJ[j][0]-sJ[p][0], ty = sJ[j][1]-sJ[p][1], tz = sJ[j][2]-sJ[p][2];
                #pragma unroll
                for (int r = 0; r < 3; r++) {
                    float p0 = sRes[p][r*4+0], p1 = sRes[p][r*4+1];
                    float p2 = sRes[p][r*4+2], p3 = sRes[p][r*4+3];
                    res[r*4+0] = p0*R[0] + p1*R[3] + p2*R[6];
                    res[r*4+1] = p0*R[1] + p1*R[4] + p2*R[7];
                    res[r*4+2] = p0*R[2] + p1*R[5] + p2*R[8];
                    res[r*4+3] = p0*tx   + p1*ty   + p2*tz + p3;
                }
            }
            #pragma unroll
            for (int i = 0; i < 12; i++) sRes[j][i] = res[i];
        }
        __syncthreads();
    }

    if (j < 24) {
        float Jx = sJ[j][0], Jy = sJ[j][1], Jz = sJ[j][2];
        float* A = &g_A[(b*24 + j) * 16];
        #pragma unroll
        for (int r = 0; r < 3; r++) {
            A[r*4+0] = res[r*4+0];
            A[r*4+1] = res[r*4+1];
            A[r*4+2] = res[r*4+2];
            A[r*4+3] = res[r*4+3] - (res[r*4+0]*Jx + res[r*4+1]*Jy + res[r*4+2]*Jz);
            outJt[b*72 + j*3 + r] = res[r*4+3];
        }
        A[12] = 0.0f; A[13] = 0.0f; A[14] = 0.0f; A[15] = 1.0f;
    }
}

// ============================= Kernel B: points ============================
__device__ __forceinline__ unsigned long long fma2(unsigned long long a,
                                                   unsigned long long b,
                                                   unsigned long long c)
{
    unsigned long long d;
    asm("fma.rn.f32x2 %0, %1, %2, %3;" : "=l"(d) : "l"(a), "l"(b), "l"(c));
    return d;
}

__global__ void __launch_bounds__(256)
pts_kernel(const float* __restrict__ ps,
           const float* __restrict__ ws,
           const void*  __restrict__ batch_raw,
           float* __restrict__ outP,
           float* __restrict__ outT,
           int N)
{
    __shared__ __align__(16) float sA[NB_MAX * 384];
    __shared__ int s_info[3];   // blo, nb, is64

    const int tid  = threadIdx.x;
    const int base = blockIdx.x * 256;

    const int*       b32 = (const int*)batch_raw;
    const long long* b64 = (const long long*)batch_raw;

    if (tid == 0) {
        // dtype probe: batch sorted, max ~B-1 (>0). If stored int64, word32[N-1]
        // is the (zero) high half of an element; if int32, it is the max value.
        int is64 = (b32[N - 1] == 0) ? 1 : 0;
        int last = base + 255; if (last > N - 1) last = N - 1;
        int blo = is64 ? (int)b64[base] : b32[base];
        int bhi = is64 ? (int)b64[last] : b32[last];
        int nb  = bhi - blo + 1; if (nb > NB_MAX) nb = NB_MAX;
        s_info[0] = blo; s_info[1] = nb; s_info[2] = is64;
    }
    __syncthreads();
    const int blo  = s_info[0];
    const int nb   = s_info[1];
    const int is64 = s_info[2];

    // cooperative stage of A16 rows [blo, blo+nb) into smem
    {
        const float4* src = reinterpret_cast<const float4*>(g_A) + blo * 96;
        float4* dst = reinterpret_cast<float4*>(sA);
        for (int i = tid; i < nb * 96; i += 256) dst[i] = __ldg(src + i);
    }
    __syncthreads();

    const int n = base + tid;
    if (n >= N) return;

    const int b = is64 ? (int)b64[n] : b32[n];

    // blend weights (24 floats, vectorized)
    float w[24];
    const float4* wsv = reinterpret_cast<const float4*>(ws + (size_t)n * 24);
    #pragma unroll
    for (int i = 0; i < 6; i++) {
        float4 v = __ldg(wsv + i);
        w[i*4+0] = v.x; w[i*4+1] = v.y; w[i*4+2] = v.z; w[i*4+3] = v.w;
    }

    unsigned long long acc[8];
    #pragma unroll
    for (int i = 0; i < 8; i++) acc[i] = 0ull;

    const int local = b - blo;
    if (local < nb) {
        unsigned aaddr = (unsigned)__cvta_generic_to_shared(sA) + (unsigned)local * 1536u;
        #pragma unroll
        for (int k = 0; k < 24; k++) {
            unsigned long long ww;
            asm("mov.b64 %0, {%1, %2};" : "=l"(ww) : "f"(w[k]), "f"(w[k]));
            unsigned ka = aaddr + (unsigned)k * 64u;
            unsigned long long a0,a1,a2,a3,a4,a5,a6,a7;
            asm volatile("ld.shared.v2.b64 {%0, %1}, [%2];"    : "=l"(a0), "=l"(a1) : "r"(ka));
            asm volatile("ld.shared.v2.b64 {%0, %1}, [%2+16];" : "=l"(a2), "=l"(a3) : "r"(ka));
            asm volatile("ld.shared.v2.b64 {%0, %1}, [%2+32];" : "=l"(a4), "=l"(a5) : "r"(ka));
            asm volatile("ld.shared.v2.b64 {%0, %1}, [%2+48];" : "=l"(a6), "=l"(a7) : "r"(ka));
            acc[0] = fma2(ww, a0, acc[0]);
            acc[1] = fma2(ww, a1, acc[1]);
            acc[2] = fma2(ww, a2, acc[2]);
            acc[3] = fma2(ww, a3, acc[3]);
            acc[4] = fma2(ww, a4, acc[4]);
            acc[5] = fma2(ww, a5, acc[5]);
            acc[6] = fma2(ww, a6, acc[6]);
            acc[7] = fma2(ww, a7, acc[7]);
        }
    } else {
        // rare fallback: batch outside the smem window — read A from global
        const float* Ab = g_A + (size_t)b * 384;
        #pragma unroll
        for (int k = 0; k < 24; k++) {
            unsigned long long ww;
            asm("mov.b64 %0, {%1, %2};" : "=l"(ww) : "f"(w[k]), "f"(w[k]));
            const float* kp = Ab + k * 16;
            unsigned long long a0,a1,a2,a3,a4,a5,a6,a7;
            asm volatile("ld.global.nc.v2.b64 {%0, %1}, [%2];"    : "=l"(a0), "=l"(a1) : "l"(kp));
            asm volatile("ld.global.nc.v2.b64 {%0, %1}, [%2+16];" : "=l"(a2), "=l"(a3) : "l"(kp));
            asm volatile("ld.global.nc.v2.b64 {%0, %1}, [%2+32];" : "=l"(a4), "=l"(a5) : "l"(kp));
            asm volatile("ld.global.nc.v2.b64 {%0, %1}, [%2+48];" : "=l"(a6), "=l"(a7) : "l"(kp));
            acc[0] = fma2(ww, a0, acc[0]);
            acc[1] = fma2(ww, a1, acc[1]);
            acc[2] = fma2(ww, a2, acc[2]);
            acc[3] = fma2(ww, a3, acc[3]);
            acc[4] = fma2(ww, a4, acc[4]);
            acc[5] = fma2(ww, a5, acc[5]);
            acc[6] = fma2(ww, a6, acc[6]);
            acc[7] = fma2(ww, a7, acc[7]);
        }
    }

    // store T (4 x 16B)
    float* Tp = outT + (size_t)n * 16;
    asm volatile("st.global.v2.b64 [%0],    {%1, %2};" :: "l"(Tp), "l"(acc[0]), "l"(acc[1]) : "memory");
    asm volatile("st.global.v2.b64 [%0+16], {%1, %2};" :: "l"(Tp), "l"(acc[2]), "l"(acc[3]) : "memory");
    asm volatile("st.global.v2.b64 [%0+32], {%1, %2};" :: "l"(Tp), "l"(acc[4]), "l"(acc[5]) : "memory");
    asm volatile("st.global.v2.b64 [%0+48], {%1, %2};" :: "l"(Tp), "l"(acc[6]), "l"(acc[7]) : "memory");

    // out3 = T[:3,:] * [p, 1]
    float t[12];
    #pragma unroll
    for (int i = 0; i < 6; i++)
        asm("mov.b64 {%0, %1}, %2;" : "=f"(t[2*i]), "=f"(t[2*i+1]) : "l"(acc[i]));

    float px = __ldg(ps + (size_t)n*3 + 0);
    float py = __ldg(ps + (size_t)n*3 + 1);
    float pz = __ldg(ps + (size_t)n*3 + 2);
    outP[(size_t)n*3 + 0] = t[0]*px + t[1]*py + t[2] *pz + t[3];
    outP[(size_t)n*3 + 1] = t[4]*px + t[5]*py + t[6] *pz + t[7];
    outP[(size_t)n*3 + 2] = t[8]*px + t[9]*py + t[10]*pz + t[11];
}

// =============================== launch ====================================
extern "C" void kernel_launch(void* const* d_in, const int* in_sizes, int n_in,
                              void* d_out, int out_size)
{
    const float* ps    = (const float*)d_in[0];
    const float* Js    = (const float*)d_in[1];
    const float* ws    = (const float*)d_in[2];
    const float* poses = (const float*)d_in[3];
    const void*  batch = d_in[4];

    const int N = in_sizes[0] / 3;
    int B = in_sizes[3] / 72;
    if (B > MAX_B) B = MAX_B;

    float* out   = (float*)d_out;
    float* outP  = out;                                  // N*3
    float* outT  = outP + (size_t)N * 3;                 // N*16
    float* outRs = outT + (size_t)N * 16;                // B*216
    float* outJt = outRs + (size_t)B * 216;              // B*72

    rig_kernel<<<B, 32>>>(Js, poses, outRs, outJt);

    const int blocks = (N + 255) / 256;
    pts_kernel<<<blocks, 256>>>(ps, ws, batch, outP, outT, N);
}